// round 5
// baseline (speedup 1.0000x reference)
#include <cuda_runtime.h>
#include <math.h>

#define NMAX 50000
#define DD 128
#define EMAX 700000
#define TR 64            // GEMM rows per block
#define ALPHA 0.2f

// ---------------- scratch (device globals, no runtime alloc) ----------------
__device__ float g_h[NMAX * DD];      // h = X @ W
__device__ float g_ssrc[NMAX];        // h . a[:D]
__device__ float g_sdst[NMAX];        // h . a[D:]
__device__ int   g_deg[NMAX];
__device__ int   g_rowptr[NMAX + 1];
__device__ int   g_cursor[NMAX];
__device__ int   g_edst[EMAX];        // CSR-sorted dst
__device__ float g_ee[EMAX];          // CSR-sorted edge_e
__device__ int   g_is64;              // 1 if edge tensor is int64

// ---------------- edge dtype detect ----------------
__global__ void detect_kernel(const int* __restrict__ e32, int E) {
    if (blockIdx.x == 0 && threadIdx.x == 0) {
        int nz = 0;
        int m = 2 * E; if (m > 2048) m = 2048;
        for (int i = 1; i < m; i += 2) nz |= e32[i];
        g_is64 = (nz == 0) ? 1 : 0;
    }
}

__device__ __forceinline__ int edge_at(const int* __restrict__ e32, int idx) {
    if (g_is64) return (int)(((const long long*)e32)[idx]);
    return e32[idx];
}

// ---------------- zero degrees ----------------
__global__ void zero_deg_kernel(int n) {
    int i = blockIdx.x * blockDim.x + threadIdx.x;
    if (i < n) g_deg[i] = 0;
}

// ---------------- GEMM + attention projections ----------------
// block: 256 threads, computes TR=64 rows x 128 cols.
// smem: W[128][128] (64KB) + X tile[64][128] (32KB) = 96KB dynamic.
__global__ void gemm_kernel(const float* __restrict__ X, const float* __restrict__ W,
                            const float* __restrict__ a, int n) {
    extern __shared__ float smem[];
    float* Ws = smem;                 // 128*128
    float* Xs = smem + DD * DD;       // 64*128
    const int base = blockIdx.x * TR;
    const int tid = threadIdx.x;

    for (int i = tid * 4; i < DD * DD; i += blockDim.x * 4)
        *(float4*)&Ws[i] = *(const float4*)&W[i];
    for (int i = tid * 4; i < TR * DD; i += blockDim.x * 4) {
        int row = base + i / DD;
        float4 v = make_float4(0.f, 0.f, 0.f, 0.f);
        if (row < n) v = *(const float4*)&X[row * DD + (i % DD)];
        *(float4*)&Xs[i] = v;
    }
    __syncthreads();

    const int lane = tid & 31;
    const int wid = tid >> 5;         // 8 warps
    const int c4 = lane * 4;          // warp covers all 128 cols
    const int r0 = wid * 8;           // 8 rows per warp

    float4 acc[8];
#pragma unroll
    for (int r = 0; r < 8; ++r) acc[r] = make_float4(0.f, 0.f, 0.f, 0.f);

#pragma unroll 4
    for (int k = 0; k < DD; ++k) {
        float4 w = *(float4*)&Ws[k * DD + c4];
#pragma unroll
        for (int r = 0; r < 8; ++r) {
            float x = Xs[(r0 + r) * DD + k];
            acc[r].x += x * w.x; acc[r].y += x * w.y;
            acc[r].z += x * w.z; acc[r].w += x * w.w;
        }
    }

    float4 aL = *(const float4*)&a[c4];
    float4 aH = *(const float4*)&a[DD + c4];
#pragma unroll
    for (int r = 0; r < 8; ++r) {
        int row = base + r0 + r;
        if (row >= n) break;          // uniform across warp
        *(float4*)&g_h[row * DD + c4] = acc[r];
        float ps = acc[r].x * aL.x + acc[r].y * aL.y + acc[r].z * aL.z + acc[r].w * aL.w;
        float pd = acc[r].x * aH.x + acc[r].y * aH.y + acc[r].z * aH.z + acc[r].w * aH.w;
#pragma unroll
        for (int o = 16; o > 0; o >>= 1) {
            ps += __shfl_xor_sync(0xffffffff, ps, o);
            pd += __shfl_xor_sync(0xffffffff, pd, o);
        }
        if (lane == 0) { g_ssrc[row] = ps; g_sdst[row] = pd; }
    }
}

// ---------------- degree histogram ----------------
__global__ void hist_kernel(const int* __restrict__ e32, int E) {
    int i = blockIdx.x * blockDim.x + threadIdx.x;
    if (i < E) atomicAdd(&g_deg[edge_at(e32, i)], 1);
}

// ---------------- exclusive scan (single block, chunked Hillis-Steele) ----------------
__global__ void scan_kernel(int n) {
    __shared__ int sh[1024];
    __shared__ int carry_s;
    const int tid = threadIdx.x;
    if (tid == 0) { carry_s = 0; g_rowptr[0] = 0; }
    __syncthreads();
    for (int base = 0; base < n; base += 1024) {
        int i = base + tid;
        int v = (i < n) ? g_deg[i] : 0;
        sh[tid] = v;
        __syncthreads();
#pragma unroll
        for (int off = 1; off < 1024; off <<= 1) {
            int t = (tid >= off) ? sh[tid - off] : 0;
            __syncthreads();
            sh[tid] += t;
            __syncthreads();
        }
        int incl = sh[tid] + carry_s;
        if (i < n) { g_rowptr[i + 1] = incl; g_cursor[i] = incl - v; }
        __syncthreads();
        if (tid == 1023) carry_s = incl;
        __syncthreads();
    }
}

// ---------------- scatter edges into CSR slots, compute edge_e ----------------
__global__ void scatter_kernel(const int* __restrict__ e32, int E) {
    int i = blockIdx.x * blockDim.x + threadIdx.x;
    if (i >= E) return;
    int s = edge_at(e32, i);
    int d = edge_at(e32, E + i);
    float sc = g_ssrc[s] + g_sdst[d];
    float lr = sc > 0.f ? sc : ALPHA * sc;
    float e = expf(lr);
    int p = atomicAdd(&g_cursor[s], 1);
    g_edst[p] = d;
    g_ee[p] = e;
}

// ---------------- gather: one warp per node, fused normalize + ELU ----------------
__global__ void gather_kernel(float* __restrict__ out, int n) {
    int gw = (blockIdx.x * blockDim.x + threadIdx.x) >> 5;
    int lane = threadIdx.x & 31;
    if (gw >= n) return;
    int beg = g_rowptr[gw], end = g_rowptr[gw + 1];
    float4 acc = make_float4(0.f, 0.f, 0.f, 0.f);
    float rs = 0.f;
    for (int p = beg; p < end; ++p) {
        float e = g_ee[p];
        int d = g_edst[p];
        float4 hv = *(const float4*)&g_h[d * DD + lane * 4];
        acc.x += e * hv.x; acc.y += e * hv.y;
        acc.z += e * hv.z; acc.w += e * hv.w;
        rs += e;
    }
    float inv = 1.0f / rs;
    float4 o;
    float vx = acc.x * inv; o.x = vx > 0.f ? vx : (expf(vx) - 1.0f);
    float vy = acc.y * inv; o.y = vy > 0.f ? vy : (expf(vy) - 1.0f);
    float vz = acc.z * inv; o.z = vz > 0.f ? vz : (expf(vz) - 1.0f);
    float vw = acc.w * inv; o.w = vw > 0.f ? vw : (expf(vw) - 1.0f);
    *(float4*)&out[gw * DD + lane * 4] = o;
}

// ---------------- launch ----------------
extern "C" void kernel_launch(void* const* d_in, const int* in_sizes, int n_in,
                              void* d_out, int out_size) {
    const float* X   = (const float*)d_in[0];
    const int*   e32 = (const int*)d_in[1];   // int32 or int64, detected on device
    const float* W   = (const float*)d_in[2];
    const float* a   = (const float*)d_in[3];
    float* out = (float*)d_out;

    int n = in_sizes[0] / DD;
    int E = in_sizes[1] / 2;

    const int smem_bytes = (DD * DD + TR * DD) * (int)sizeof(float);  // 96KB
    cudaFuncSetAttribute(gemm_kernel, cudaFuncAttributeMaxDynamicSharedMemorySize, smem_bytes);

    detect_kernel<<<1, 32>>>(e32, E);
    zero_deg_kernel<<<(n + 255) / 256, 256>>>(n);
    gemm_kernel<<<(n + TR - 1) / TR, 256, smem_bytes>>>(X, W, a, n);
    hist_kernel<<<(E + 255) / 256, 256>>>(e32, E);
    scan_kernel<<<1, 1024>>>(n);
    scatter_kernel<<<(E + 255) / 256, 256>>>(e32, E);
    gather_kernel<<<((long long)n * 32 + 255) / 256, 256>>>(out, n);
}

// round 6
// speedup vs baseline: 1.7222x; 1.7222x over previous
#include <cuda_runtime.h>
#include <math.h>

#define NMAX 50000
#define DD 128
#define EMAX 700000
#define TR 64            // GEMM rows per block
#define ALPHA 0.2f

// ---------------- scratch (device globals, no runtime alloc) ----------------
__device__ float g_h[NMAX * DD];      // h = X @ W
__device__ float g_ssrc[NMAX];        // h . a[:D]
__device__ float g_sdst[NMAX];        // h . a[D:]
__device__ int   g_deg[NMAX];
__device__ int   g_rowptr[NMAX + 1];
__device__ int   g_cursor[NMAX];
__device__ int   g_edst[EMAX];        // CSR-sorted dst
__device__ int   g_part[256];         // block partial sums for scan
__device__ int   g_is64;              // 1 if edge tensor is int64

// ---------------- init: zero degrees + detect edge dtype ----------------
__global__ void init_kernel(const int* __restrict__ e32, int E, int n) {
    int i = blockIdx.x * blockDim.x + threadIdx.x;
    if (i < n) g_deg[i] = 0;
    if (blockIdx.x == 0 && threadIdx.x < 32) {
        // int64 little-endian => odd 32-bit words are high words (all zero for ids < 2^31)
        int nz = 0;
        int m = 2 * E; if (m > 4096) m = 4096;
        for (int j = 1 + 2 * (int)threadIdx.x; j < m; j += 64) nz |= e32[j];
#pragma unroll
        for (int o = 16; o > 0; o >>= 1) nz |= __shfl_xor_sync(0xffffffffu, nz, o);
        if (threadIdx.x == 0) g_is64 = (nz == 0) ? 1 : 0;
    }
}

// ---------------- GEMM + attention projections (packed f32x2 FFMA) ----------
// block: 256 threads, computes TR=64 rows x 128 cols.
// smem: W[128][128] (64KB) + X tile[64][128] (32KB) = 96KB dynamic.
__global__ void __launch_bounds__(256, 2)
gemm_kernel(const float* __restrict__ X, const float* __restrict__ W,
            const float* __restrict__ a, int n) {
    extern __shared__ float smem[];
    float* Ws = smem;                 // 128*128
    float* Xs = smem + DD * DD;       // 64*128
    const int base = blockIdx.x * TR;
    const int tid = threadIdx.x;

    for (int i = tid * 4; i < DD * DD; i += blockDim.x * 4)
        *(float4*)&Ws[i] = *(const float4*)&W[i];
    for (int i = tid * 4; i < TR * DD; i += blockDim.x * 4) {
        int row = base + i / DD;
        float4 v = make_float4(0.f, 0.f, 0.f, 0.f);
        if (row < n) v = *(const float4*)&X[row * DD + (i % DD)];
        *(float4*)&Xs[i] = v;
    }
    __syncthreads();

    const int lane = tid & 31;
    const int wid = tid >> 5;         // 8 warps
    const int c4 = lane * 4;          // warp covers all 128 cols
    const int r0 = wid * 8;           // 8 rows per warp

    unsigned long long acc0[8], acc1[8];   // packed (f32,f32) accumulators
#pragma unroll
    for (int r = 0; r < 8; ++r) { acc0[r] = 0ull; acc1[r] = 0ull; }

    for (int k = 0; k < DD; k += 4) {
        float4 xv[8];
#pragma unroll
        for (int r = 0; r < 8; ++r)
            xv[r] = *(const float4*)&Xs[(r0 + r) * DD + k];   // broadcast within warp
#pragma unroll
        for (int kk = 0; kk < 4; ++kk) {
            ulonglong2 wp = *(const ulonglong2*)&Ws[(k + kk) * DD + c4];
#pragma unroll
            for (int r = 0; r < 8; ++r) {
                float x = (kk == 0) ? xv[r].x : (kk == 1) ? xv[r].y
                         : (kk == 2) ? xv[r].z : xv[r].w;
                unsigned long long xx;
                asm("mov.b64 %0, {%1, %1};" : "=l"(xx) : "f"(x));
                asm("fma.rn.f32x2 %0, %1, %2, %0;" : "+l"(acc0[r]) : "l"(xx), "l"(wp.x));
                asm("fma.rn.f32x2 %0, %1, %2, %0;" : "+l"(acc1[r]) : "l"(xx), "l"(wp.y));
            }
        }
    }

    float4 aL = *(const float4*)&a[c4];
    float4 aH = *(const float4*)&a[DD + c4];
#pragma unroll
    for (int r = 0; r < 8; ++r) {
        int row = base + r0 + r;
        if (row >= n) break;          // uniform across warp
        float4 c;
        asm("mov.b64 {%0, %1}, %2;" : "=f"(c.x), "=f"(c.y) : "l"(acc0[r]));
        asm("mov.b64 {%0, %1}, %2;" : "=f"(c.z), "=f"(c.w) : "l"(acc1[r]));
        *(float4*)&g_h[row * DD + c4] = c;
        float ps = c.x * aL.x + c.y * aL.y + c.z * aL.z + c.w * aL.w;
        float pd = c.x * aH.x + c.y * aH.y + c.z * aH.z + c.w * aH.w;
#pragma unroll
        for (int o = 16; o > 0; o >>= 1) {
            ps += __shfl_xor_sync(0xffffffff, ps, o);
            pd += __shfl_xor_sync(0xffffffff, pd, o);
        }
        if (lane == 0) { g_ssrc[row] = ps; g_sdst[row] = pd; }
    }
}

// ---------------- degree histogram (4 edges/thread for MLP) ----------------
__global__ void hist_kernel(const int* __restrict__ e32, int E) {
    const int mult = g_is64 ? 2 : 1;
    int i0 = (blockIdx.x * blockDim.x + threadIdx.x) * 4;
    int s[4];
#pragma unroll
    for (int j = 0; j < 4; ++j) {
        int i = i0 + j;
        s[j] = (i < E) ? e32[(long long)i * mult] : -1;
    }
#pragma unroll
    for (int j = 0; j < 4; ++j)
        if (s[j] >= 0) atomicAdd(&g_deg[s[j]], 1);
}

// ---------------- 3-pass exclusive scan over g_deg -------------------------
__global__ void scan1_kernel(int n) {
    const int tid = threadIdx.x;
    const int lane = tid & 31, wid = tid >> 5;
    int i = blockIdx.x * 256 + tid;
    int v = (i < n) ? g_deg[i] : 0;
    int s = v;
#pragma unroll
    for (int off = 1; off < 32; off <<= 1) {
        int t = __shfl_up_sync(0xffffffffu, s, off);
        if (lane >= off) s += t;
    }
    __shared__ int wtot[8], woff[8];
    if (lane == 31) wtot[wid] = s;
    __syncthreads();
    if (tid == 0) {
        int run = 0;
#pragma unroll
        for (int w = 0; w < 8; ++w) { woff[w] = run; run += wtot[w]; }
        g_part[blockIdx.x] = run;
        if (blockIdx.x == 0) g_rowptr[0] = 0;
    }
    __syncthreads();
    if (i < n) g_rowptr[i + 1] = s + woff[wid];   // block-local inclusive
}

__global__ void scan2_kernel(int nb) {
    const int tid = threadIdx.x;
    const int lane = tid & 31, wid = tid >> 5;
    int v = (tid < nb) ? g_part[tid] : 0;
    int s = v;
#pragma unroll
    for (int off = 1; off < 32; off <<= 1) {
        int t = __shfl_up_sync(0xffffffffu, s, off);
        if (lane >= off) s += t;
    }
    __shared__ int wtot[8], woff[8];
    if (lane == 31) wtot[wid] = s;
    __syncthreads();
    if (tid == 0) {
        int run = 0;
#pragma unroll
        for (int w = 0; w < 8; ++w) { woff[w] = run; run += wtot[w]; }
    }
    __syncthreads();
    if (tid < nb) g_part[tid] = s - v + woff[wid];  // exclusive block offsets
}

__global__ void scan3_kernel(int n) {
    int i = blockIdx.x * 256 + threadIdx.x;
    if (i < n) {
        int incl = g_rowptr[i + 1] + g_part[blockIdx.x];
        g_rowptr[i + 1] = incl;
        g_cursor[i] = incl - g_deg[i];
    }
}

// ---------------- scatter dst into CSR slots (4 edges/thread) --------------
__global__ void scatter_kernel(const int* __restrict__ e32, int E) {
    const int mult = g_is64 ? 2 : 1;
    int i0 = (blockIdx.x * blockDim.x + threadIdx.x) * 4;
    int s[4], d[4];
#pragma unroll
    for (int j = 0; j < 4; ++j) {
        int i = i0 + j;
        if (i < E) {
            s[j] = e32[(long long)i * mult];
            d[j] = e32[(long long)(E + i) * mult];
        } else s[j] = -1;
    }
#pragma unroll
    for (int j = 0; j < 4; ++j) {
        if (s[j] >= 0) {
            int p = atomicAdd(&g_cursor[s[j]], 1);
            g_edst[p] = d[j];
        }
    }
}

// ---------------- gather: warp/node, on-the-fly edge weights, fused ELU ----
__global__ void gather_kernel(float* __restrict__ out, int n) {
    int gw = (blockIdx.x * blockDim.x + threadIdx.x) >> 5;
    int lane = threadIdx.x & 31;
    if (gw >= n) return;
    int beg = g_rowptr[gw], end = g_rowptr[gw + 1];
    float ss = g_ssrc[gw];
    float4 acc = make_float4(0.f, 0.f, 0.f, 0.f);
    float rs = 0.f;
    for (int p = beg; p < end; ++p) {
        int d = g_edst[p];                       // broadcast
        float sc = ss + g_sdst[d];               // broadcast
        float lr = sc > 0.f ? sc : ALPHA * sc;
        float e = expf(lr);
        float4 hv = *(const float4*)&g_h[d * DD + lane * 4];
        acc.x += e * hv.x; acc.y += e * hv.y;
        acc.z += e * hv.z; acc.w += e * hv.w;
        rs += e;
    }
    float inv = 1.0f / rs;
    float4 o;
    float vx = acc.x * inv; o.x = vx > 0.f ? vx : (expf(vx) - 1.0f);
    float vy = acc.y * inv; o.y = vy > 0.f ? vy : (expf(vy) - 1.0f);
    float vz = acc.z * inv; o.z = vz > 0.f ? vz : (expf(vz) - 1.0f);
    float vw = acc.w * inv; o.w = vw > 0.f ? vw : (expf(vw) - 1.0f);
    *(float4*)&out[gw * DD + lane * 4] = o;
}

// ---------------- launch ----------------
extern "C" void kernel_launch(void* const* d_in, const int* in_sizes, int n_in,
                              void* d_out, int out_size) {
    const float* X   = (const float*)d_in[0];
    const int*   e32 = (const int*)d_in[1];   // int32 or int64, detected on device
    const float* W   = (const float*)d_in[2];
    const float* a   = (const float*)d_in[3];
    float* out = (float*)d_out;

    int n = in_sizes[0] / DD;
    int E = in_sizes[1] / 2;
    int nb = (n + 255) / 256;

    const int smem_bytes = (DD * DD + TR * DD) * (int)sizeof(float);  // 96KB
    cudaFuncSetAttribute(gemm_kernel, cudaFuncAttributeMaxDynamicSharedMemorySize, smem_bytes);

    init_kernel<<<nb, 256>>>(e32, E, n);
    gemm_kernel<<<(n + TR - 1) / TR, 256, smem_bytes>>>(X, W, a, n);
    hist_kernel<<<(E + 1023) / 1024, 256>>>(e32, E);
    scan1_kernel<<<nb, 256>>>(n);
    scan2_kernel<<<1, 256>>>(nb);
    scan3_kernel<<<nb, 256>>>(n);
    scatter_kernel<<<(E + 1023) / 1024, 256>>>(e32, E);
    gather_kernel<<<((long long)n * 32 + 255) / 256, 256>>>(out, n);
}

// round 7
// speedup vs baseline: 2.0545x; 1.1929x over previous
#include <cuda_runtime.h>
#include <math.h>

#define NMAX 50000
#define DD 128
#define EMAX 700000
#define TR 64            // GEMM rows per block
#define ALPHA 0.2f

// ---------------- scratch (device globals, no runtime alloc) ----------------
__device__ float g_h[NMAX * DD];      // h = X @ W
__device__ float g_ssrc[NMAX];        // h . a[:D]
__device__ float g_sdst[NMAX];        // h . a[D:]
__device__ int   g_deg[NMAX];
__device__ int   g_rowptr[NMAX + 1];
__device__ int   g_cursor[NMAX];
__device__ int   g_edst[EMAX];        // CSR-sorted dst
__device__ int   g_part[256];         // block partial sums for scan
__device__ int   g_is64;              // 1 if edge tensor is int64

// ---------------- side stream + fork/join events (created once, pre-main) --
static cudaStream_t g_s2;
static cudaEvent_t  g_evFork, g_evJoin;
static struct StreamInit {
    StreamInit() {
        cudaStreamCreateWithFlags(&g_s2, cudaStreamNonBlocking);
        cudaEventCreateWithFlags(&g_evFork, cudaEventDisableTiming);
        cudaEventCreateWithFlags(&g_evJoin, cudaEventDisableTiming);
    }
} g_streamInit;

// ---------------- init: zero degrees + detect edge dtype ----------------
__global__ void init_kernel(const int* __restrict__ e32, int E, int n) {
    int i = blockIdx.x * blockDim.x + threadIdx.x;
    if (i < n) g_deg[i] = 0;
    if (blockIdx.x == 0 && threadIdx.x < 32) {
        // int64 little-endian => odd 32-bit words are high words (all zero for ids < 2^31)
        int nz = 0;
        int m = 2 * E; if (m > 4096) m = 4096;
        for (int j = 1 + 2 * (int)threadIdx.x; j < m; j += 64) nz |= e32[j];
#pragma unroll
        for (int o = 16; o > 0; o >>= 1) nz |= __shfl_xor_sync(0xffffffffu, nz, o);
        if (threadIdx.x == 0) g_is64 = (nz == 0) ? 1 : 0;
    }
}

// ---------------- GEMM + attention projections (packed f32x2 FFMA) ----------
// block: 256 threads, computes TR=64 rows x 128 cols.
// smem: W[128][128] (64KB) + X tile[64][128] (32KB) = 96KB dynamic.
__global__ void __launch_bounds__(256, 2)
gemm_kernel(const float* __restrict__ X, const float* __restrict__ W,
            const float* __restrict__ a, int n) {
    extern __shared__ float smem[];
    float* Ws = smem;                 // 128*128
    float* Xs = smem + DD * DD;       // 64*128
    const int base = blockIdx.x * TR;
    const int tid = threadIdx.x;

    for (int i = tid * 4; i < DD * DD; i += blockDim.x * 4)
        *(float4*)&Ws[i] = *(const float4*)&W[i];
    for (int i = tid * 4; i < TR * DD; i += blockDim.x * 4) {
        int row = base + i / DD;
        float4 v = make_float4(0.f, 0.f, 0.f, 0.f);
        if (row < n) v = *(const float4*)&X[row * DD + (i % DD)];
        *(float4*)&Xs[i] = v;
    }
    __syncthreads();

    const int lane = tid & 31;
    const int wid = tid >> 5;         // 8 warps
    const int c4 = lane * 4;          // warp covers all 128 cols
    const int r0 = wid * 8;           // 8 rows per warp

    unsigned long long acc0[8], acc1[8];   // packed (f32,f32) accumulators
#pragma unroll
    for (int r = 0; r < 8; ++r) { acc0[r] = 0ull; acc1[r] = 0ull; }

    for (int k = 0; k < DD; k += 4) {
        float4 xv[8];
#pragma unroll
        for (int r = 0; r < 8; ++r)
            xv[r] = *(const float4*)&Xs[(r0 + r) * DD + k];   // broadcast within warp
#pragma unroll
        for (int kk = 0; kk < 4; ++kk) {
            ulonglong2 wp = *(const ulonglong2*)&Ws[(k + kk) * DD + c4];
#pragma unroll
            for (int r = 0; r < 8; ++r) {
                float x = (kk == 0) ? xv[r].x : (kk == 1) ? xv[r].y
                         : (kk == 2) ? xv[r].z : xv[r].w;
                unsigned long long xx;
                asm("mov.b64 %0, {%1, %1};" : "=l"(xx) : "f"(x));
                asm("fma.rn.f32x2 %0, %1, %2, %0;" : "+l"(acc0[r]) : "l"(xx), "l"(wp.x));
                asm("fma.rn.f32x2 %0, %1, %2, %0;" : "+l"(acc1[r]) : "l"(xx), "l"(wp.y));
            }
        }
    }

    float4 aL = *(const float4*)&a[c4];
    float4 aH = *(const float4*)&a[DD + c4];
#pragma unroll
    for (int r = 0; r < 8; ++r) {
        int row = base + r0 + r;
        if (row >= n) break;          // uniform across warp
        float4 c;
        asm("mov.b64 {%0, %1}, %2;" : "=f"(c.x), "=f"(c.y) : "l"(acc0[r]));
        asm("mov.b64 {%0, %1}, %2;" : "=f"(c.z), "=f"(c.w) : "l"(acc1[r]));
        *(float4*)&g_h[row * DD + c4] = c;
        float ps = c.x * aL.x + c.y * aL.y + c.z * aL.z + c.w * aL.w;
        float pd = c.x * aH.x + c.y * aH.y + c.z * aH.z + c.w * aH.w;
#pragma unroll
        for (int o = 16; o > 0; o >>= 1) {
            ps += __shfl_xor_sync(0xffffffff, ps, o);
            pd += __shfl_xor_sync(0xffffffff, pd, o);
        }
        if (lane == 0) { g_ssrc[row] = ps; g_sdst[row] = pd; }
    }
}

// ---------------- degree histogram (4 edges/thread for MLP) ----------------
__global__ void hist_kernel(const int* __restrict__ e32, int E) {
    const int mult = g_is64 ? 2 : 1;
    int i0 = (blockIdx.x * blockDim.x + threadIdx.x) * 4;
    int s[4];
#pragma unroll
    for (int j = 0; j < 4; ++j) {
        int i = i0 + j;
        s[j] = (i < E) ? e32[(long long)i * mult] : -1;
    }
#pragma unroll
    for (int j = 0; j < 4; ++j)
        if (s[j] >= 0) atomicAdd(&g_deg[s[j]], 1);
}

// ---------------- 2-pass exclusive scan over g_deg -------------------------
__global__ void scan1_kernel(int n) {
    const int tid = threadIdx.x;
    const int lane = tid & 31, wid = tid >> 5;
    int i = blockIdx.x * 256 + tid;
    int v = (i < n) ? g_deg[i] : 0;
    int s = v;
#pragma unroll
    for (int off = 1; off < 32; off <<= 1) {
        int t = __shfl_up_sync(0xffffffffu, s, off);
        if (lane >= off) s += t;
    }
    __shared__ int wtot[8], woff[8];
    if (lane == 31) wtot[wid] = s;
    __syncthreads();
    if (tid == 0) {
        int run = 0;
#pragma unroll
        for (int w = 0; w < 8; ++w) { woff[w] = run; run += wtot[w]; }
        g_part[blockIdx.x] = run;
        if (blockIdx.x == 0) g_rowptr[0] = 0;
    }
    __syncthreads();
    if (i < n) g_rowptr[i + 1] = s + woff[wid];   // block-local inclusive
}

// scan2+scan3 fused: every block redundantly scans the <=256 block partials
// (196 ints -- trivial), picks its own exclusive offset, applies it.
__global__ void scan23_kernel(int n, int nb) {
    const int tid = threadIdx.x;
    const int lane = tid & 31, wid = tid >> 5;
    int v = (tid < nb) ? g_part[tid] : 0;
    int s = v;
#pragma unroll
    for (int off = 1; off < 32; off <<= 1) {
        int t = __shfl_up_sync(0xffffffffu, s, off);
        if (lane >= off) s += t;
    }
    __shared__ int wtot[8], woff[8];
    __shared__ int sh_excl[256];
    if (lane == 31) wtot[wid] = s;
    __syncthreads();
    if (tid == 0) {
        int run = 0;
#pragma unroll
        for (int w = 0; w < 8; ++w) { woff[w] = run; run += wtot[w]; }
    }
    __syncthreads();
    sh_excl[tid] = s - v + woff[wid];             // exclusive offsets
    __syncthreads();
    int blockOff = sh_excl[blockIdx.x];
    int i = blockIdx.x * 256 + tid;
    if (i < n) {
        int incl = g_rowptr[i + 1] + blockOff;
        g_rowptr[i + 1] = incl;
        g_cursor[i] = incl - g_deg[i];
    }
}

// ---------------- scatter dst into CSR slots (4 edges/thread) --------------
__global__ void scatter_kernel(const int* __restrict__ e32, int E) {
    const int mult = g_is64 ? 2 : 1;
    int i0 = (blockIdx.x * blockDim.x + threadIdx.x) * 4;
    int s[4], d[4];
#pragma unroll
    for (int j = 0; j < 4; ++j) {
        int i = i0 + j;
        if (i < E) {
            s[j] = e32[(long long)i * mult];
            d[j] = e32[(long long)(E + i) * mult];
        } else s[j] = -1;
    }
#pragma unroll
    for (int j = 0; j < 4; ++j) {
        if (s[j] >= 0) {
            int p = atomicAdd(&g_cursor[s[j]], 1);
            g_edst[p] = d[j];
        }
    }
}

// ---------------- gather: warp/node, on-the-fly weights, 2x unroll, ELU ----
__global__ void gather_kernel(float* __restrict__ out, int n) {
    int gw = (blockIdx.x * blockDim.x + threadIdx.x) >> 5;
    int lane = threadIdx.x & 31;
    if (gw >= n) return;
    int beg = g_rowptr[gw], end = g_rowptr[gw + 1];
    float ss = g_ssrc[gw];
    float4 acc0 = make_float4(0.f, 0.f, 0.f, 0.f);
    float4 acc1 = make_float4(0.f, 0.f, 0.f, 0.f);
    float rs0 = 0.f, rs1 = 0.f;
    int p = beg;
    for (; p + 2 <= end; p += 2) {
        int d0 = g_edst[p];                      // broadcast
        int d1 = g_edst[p + 1];
        float4 h0 = *(const float4*)&g_h[d0 * DD + lane * 4];
        float4 h1 = *(const float4*)&g_h[d1 * DD + lane * 4];
        float sc0 = ss + g_sdst[d0];
        float sc1 = ss + g_sdst[d1];
        float lr0 = sc0 > 0.f ? sc0 : ALPHA * sc0;
        float lr1 = sc1 > 0.f ? sc1 : ALPHA * sc1;
        float e0 = expf(lr0);
        float e1 = expf(lr1);
        acc0.x += e0 * h0.x; acc0.y += e0 * h0.y;
        acc0.z += e0 * h0.z; acc0.w += e0 * h0.w;
        acc1.x += e1 * h1.x; acc1.y += e1 * h1.y;
        acc1.z += e1 * h1.z; acc1.w += e1 * h1.w;
        rs0 += e0; rs1 += e1;
    }
    if (p < end) {
        int d = g_edst[p];
        float sc = ss + g_sdst[d];
        float lr = sc > 0.f ? sc : ALPHA * sc;
        float e = expf(lr);
        float4 hv = *(const float4*)&g_h[d * DD + lane * 4];
        acc0.x += e * hv.x; acc0.y += e * hv.y;
        acc0.z += e * hv.z; acc0.w += e * hv.w;
        rs0 += e;
    }
    float inv = 1.0f / (rs0 + rs1);
    float4 o;
    float vx = (acc0.x + acc1.x) * inv; o.x = vx > 0.f ? vx : (expf(vx) - 1.0f);
    float vy = (acc0.y + acc1.y) * inv; o.y = vy > 0.f ? vy : (expf(vy) - 1.0f);
    float vz = (acc0.z + acc1.z) * inv; o.z = vz > 0.f ? vz : (expf(vz) - 1.0f);
    float vw = (acc0.w + acc1.w) * inv; o.w = vw > 0.f ? vw : (expf(vw) - 1.0f);
    *(float4*)&out[gw * DD + lane * 4] = o;
}

// ---------------- launch ----------------
extern "C" void kernel_launch(void* const* d_in, const int* in_sizes, int n_in,
                              void* d_out, int out_size) {
    const float* X   = (const float*)d_in[0];
    const int*   e32 = (const int*)d_in[1];   // int32 or int64, detected on device
    const float* W   = (const float*)d_in[2];
    const float* a   = (const float*)d_in[3];
    float* out = (float*)d_out;

    int n = in_sizes[0] / DD;
    int E = in_sizes[1] / 2;
    int nb = (n + 255) / 256;

    const int smem_bytes = (DD * DD + TR * DD) * (int)sizeof(float);  // 96KB
    cudaFuncSetAttribute(gemm_kernel, cudaFuncAttributeMaxDynamicSharedMemorySize, smem_bytes);

    // Fork: CSR-build chain (independent of GEMM) runs on side stream.
    cudaEventRecord(g_evFork, 0);
    cudaStreamWaitEvent(g_s2, g_evFork, 0);

    init_kernel   <<<nb, 256, 0, g_s2>>>(e32, E, n);
    hist_kernel   <<<(E + 1023) / 1024, 256, 0, g_s2>>>(e32, E);
    scan1_kernel  <<<nb, 256, 0, g_s2>>>(n);
    scan23_kernel <<<nb, 256, 0, g_s2>>>(n, nb);
    scatter_kernel<<<(E + 1023) / 1024, 256, 0, g_s2>>>(e32, E);
    cudaEventRecord(g_evJoin, g_s2);

    // Main stream: GEMM overlaps the CSR build.
    gemm_kernel<<<(n + TR - 1) / TR, 256, smem_bytes>>>(X, W, a, n);

    // Join, then gather (needs both h/scores and CSR).
    cudaStreamWaitEvent(0, g_evJoin, 0);
    gather_kernel<<<((long long)n * 32 + 255) / 256, 256>>>(out, n);
}